// round 4
// baseline (speedup 1.0000x reference)
#include <cuda_runtime.h>
#include <cuda_bf16.h>
#include <math.h>

#define N_NODES_MAX 200000
#define N_QUERY_MAX 131072
#define FEAT 9
#define HID 64
#define OUT 128

typedef unsigned long long ull;

// ---------------- static device scratch ----------------
__device__ float4 g_geom4[N_NODES_MAX];
__device__ float  g_feat[FEAT * N_QUERY_MAX];   // column-major [FEAT][Q]
__device__ double g_sums[2 * FEAT];

// ---------------- f32x2 helpers ----------------
__device__ __forceinline__ ull pk2(float lo, float hi) {
    ull r; asm("mov.b64 %0,{%1,%2};" : "=l"(r) : "f"(lo), "f"(hi)); return r;
}
__device__ __forceinline__ void upk2(float& lo, float& hi, ull v) {
    asm("mov.b64 {%0,%1},%2;" : "=f"(lo), "=f"(hi) : "l"(v));
}
__device__ __forceinline__ ull fma2(ull a, ull b, ull c) {
    ull d; asm("fma.rn.f32x2 %0,%1,%2,%3;" : "=l"(d) : "l"(a), "l"(b), "l"(c));
    return d;
}

// ---------------- K1: pad geometry + zero accumulators ----------------
__global__ void prep_kernel(const float* __restrict__ geom, int n) {
    int i = blockIdx.x * blockDim.x + threadIdx.x;
    if (blockIdx.x == 0 && threadIdx.x < 2 * FEAT) g_sums[threadIdx.x] = 0.0;
    if (i < n) {
        float4 p;
        p.x = geom[3 * i + 0];
        p.y = geom[3 * i + 1];
        p.z = geom[3 * i + 2];
        p.w = 0.f;
        g_geom4[i] = p;
    }
}

// ---------------- K2: fused moments + features + column reduction ----------------
__global__ __launch_bounds__(256)
void moments_feat_kernel(const float* __restrict__ lq,
                         const int* __restrict__ nidx,
                         const int* __restrict__ rs,
                         int Qn) {
    int q = blockIdx.x * blockDim.x + threadIdx.x;
    bool valid = (q < Qn);
    int qc = valid ? q : (Qn - 1);

    float f[FEAT];
#pragma unroll
    for (int i = 0; i < FEAT; i++) f[i] = 0.f;

    {
        int start = rs[qc];
        int end   = rs[qc + 1];
        int cnt   = end - start;

        float qx = __ldg(&lq[3 * qc + 0]);
        float qy = __ldg(&lq[3 * qc + 1]);
        float qz = __ldg(&lq[3 * qc + 2]);

        float sd = 0.f, sd2 = 0.f;
        float sx = 0.f, sy = 0.f, sz = 0.f;
        float sxx = 0.f, sxy = 0.f, sxz = 0.f, syy = 0.f, syz = 0.f, szz = 0.f;

        if (cnt == 32 && (start & 3) == 0) {
            const int4* ip = (const int4*)(nidx + start);
            int4 iv[8];
#pragma unroll
            for (int i = 0; i < 8; i++) iv[i] = __ldg(&ip[i]);
            const int* idf = (const int*)iv;
#pragma unroll
            for (int e = 0; e < 32; e++) {
                float4 p = g_geom4[idf[e]];
                float dx = p.x - qx, dy = p.y - qy, dz = p.z - qz;
                float d2 = dx * dx + dy * dy + dz * dz;
                sd  += sqrtf(d2);
                sd2 += d2;
                sx += p.x; sy += p.y; sz += p.z;
                sxx += p.x * p.x; sxy += p.x * p.y; sxz += p.x * p.z;
                syy += p.y * p.y; syz += p.y * p.z; szz += p.z * p.z;
            }
        } else {
            for (int e = start; e < end; e++) {
                int id = __ldg(&nidx[e]);
                float4 p = g_geom4[id];
                float dx = p.x - qx, dy = p.y - qy, dz = p.z - qz;
                float d2 = dx * dx + dy * dy + dz * dz;
                sd  += sqrtf(d2);
                sd2 += d2;
                sx += p.x; sy += p.y; sz += p.z;
                sxx += p.x * p.x; sxy += p.x * p.y; sxz += p.x * p.z;
                syy += p.y * p.y; syz += p.y * p.z; szz += p.z * p.z;
            }
        }

        if (valid && cnt > 0) {
            float fcnt = (float)cnt;
            float inv = 1.f / fmaxf(fcnt, 1.f);

            float davg = sd * inv;
            float ex2  = sd2 * inv;
            float dvar = fmaxf(ex2 - davg * davg, 0.f);

            float cx = sx * inv, cy = sy * inv, cz = sz * inv;

            float a = sxx * inv - cx * cx;
            float b = syy * inv - cy * cy;
            float c = szz * inv - cz * cz;
            float d = sxy * inv - cx * cy;
            float e = sxz * inv - cx * cz;
            float ff = syz * inv - cy * cz;

            float e1, e2, e3;
            float p1 = d * d + e * e + ff * ff;
            float qm = (a + b + c) * (1.f / 3.f);
            float aa = a - qm, bb = b - qm, cc = c - qm;
            float p2 = aa * aa + bb * bb + cc * cc + 2.f * p1;
            if (p2 <= 1e-22f) {
                e1 = e2 = e3 = qm;
            } else {
                float p = sqrtf(p2 * (1.f / 6.f));
                float ipv = 1.f / p;
                float b11 = aa * ipv, b22 = bb * ipv, b33 = cc * ipv;
                float b12 = d * ipv, b13 = e * ipv, b23 = ff * ipv;
                float r = 0.5f * (b11 * (b22 * b33 - b23 * b23)
                                - b12 * (b12 * b33 - b23 * b13)
                                + b13 * (b12 * b23 - b22 * b13));
                r = fminf(fmaxf(r, -1.f), 1.f);
                float phi = acosf(r) * (1.f / 3.f);
                e1 = qm + 2.f * p * cosf(phi);
                e3 = qm + 2.f * p * cosf(phi + 2.0943951023931953f);
                e2 = 3.f * qm - e1 - e3;
            }

            f[0] = fcnt; f[1] = davg; f[2] = dvar;
            f[3] = cx - qx; f[4] = cy - qy; f[5] = cz - qz;
            f[6] = e1; f[7] = e2; f[8] = e3;
        }
    }

    if (valid) {
#pragma unroll
        for (int i = 0; i < FEAT; i++) g_feat[i * N_QUERY_MAX + q] = f[i];
    }

    // block reduction of column sums/sumsqs in double
    double s[FEAT], s2[FEAT];
#pragma unroll
    for (int i = 0; i < FEAT; i++) {
        double v = valid ? (double)f[i] : 0.0;
        s[i] = v; s2[i] = v * v;
    }
#pragma unroll
    for (int i = 0; i < FEAT; i++) {
#pragma unroll
        for (int o = 16; o; o >>= 1) {
            s[i]  += __shfl_xor_sync(0xffffffffu, s[i], o);
            s2[i] += __shfl_xor_sync(0xffffffffu, s2[i], o);
        }
    }

    __shared__ double red[8][2 * FEAT];
    int warp = threadIdx.x >> 5, lane = threadIdx.x & 31;
    if (lane == 0) {
#pragma unroll
        for (int i = 0; i < FEAT; i++) {
            red[warp][i] = s[i];
            red[warp][FEAT + i] = s2[i];
        }
    }
    __syncthreads();
    if (threadIdx.x < 2 * FEAT) {
        double t = 0.0;
#pragma unroll
        for (int w = 0; w < 8; w++) t += red[w][threadIdx.x];
        atomicAdd(&g_sums[threadIdx.x], t);
    }
}

// ---------------- K3: fused MLP (packed f32x2, h in shared) ----------------
#define QB 128
#define OFF_W2   0                      // 8192
#define OFF_W1   (OFF_W2 + HID * OUT)   // 576
#define OFF_B1   (OFF_W1 + FEAT * HID)  // 64
#define OFF_B2   (OFF_B1 + HID)         // 128
#define OFF_NRM  (OFF_B2 + OUT)         // 32 (mean[9], invstd[9], pad)
#define OFF_H    (OFF_NRM + 32)         // 64 * 128 = 8192
#define OFF_STG  (OFF_H + HID * QB)     // 32 * 129 = 4128
#define STG_STRIDE 129
#define MLP_SMEM_FLOATS (OFF_STG + 32 * STG_STRIDE)
#define MLP_SMEM_BYTES  (MLP_SMEM_FLOATS * 4)

__global__ __launch_bounds__(QB, 2)
void mlp_kernel(const float* __restrict__ gW1, const float* __restrict__ gb1,
                const float* __restrict__ gW2, const float* __restrict__ gb2,
                float* __restrict__ out, int Qn) {
    extern __shared__ float sm[];
    int tid = threadIdx.x;

    {
        const float4* w2v = (const float4*)gW2;
        float4* d = (float4*)&sm[OFF_W2];
#pragma unroll
        for (int i = 0; i < (HID * OUT / 4) / QB; i++)
            d[tid + i * QB] = w2v[tid + i * QB];
        for (int i = tid; i < FEAT * HID; i += QB) sm[OFF_W1 + i] = gW1[i];
        if (tid < HID) sm[OFF_B1 + tid] = gb1[tid];
        if (tid < OUT) sm[OFF_B2 + tid] = gb2[tid];
        if (tid < FEAT) {
            double Qd = (double)Qn;
            double mean = g_sums[tid] / Qd;
            double var = (g_sums[FEAT + tid] - Qd * mean * mean) / (Qd - 1.0);
            if (var < 0.0) var = 0.0;
            double sd = sqrt(var);
            sm[OFF_NRM + tid] = (float)mean;
            sm[OFF_NRM + FEAT + tid] = (sd < 1e-6) ? 1.0f : (float)(1.0 / sd);
        }
    }
    __syncthreads();

    int qb = blockIdx.x * QB;
    int q = qb + tid;
    int qc = (q < Qn) ? q : (Qn - 1);

    // normalized features (coalesced column-major loads), splat-packed
    ull fnp[FEAT];
#pragma unroll
    for (int i = 0; i < FEAT; i++) {
        float v = (g_feat[i * N_QUERY_MAX + qc] - sm[OFF_NRM + i]) * sm[OFF_NRM + FEAT + i];
        fnp[i] = pk2(v, v);
    }

    // layer 1: h -> shared, layout hs[k][tid] (stride QB, conflict-free)
    float* hs = &sm[OFF_H];
#pragma unroll
    for (int op = 0; op < HID / 2; op++) {
        ull acc = *(const ull*)&sm[OFF_B1 + 2 * op];
#pragma unroll
        for (int ff = 0; ff < FEAT; ff++)
            acc = fma2(fnp[ff], *(const ull*)&sm[OFF_W1 + ff * HID + 2 * op], acc);
        float lo, hi; upk2(lo, hi, acc);
        hs[(2 * op) * QB + tid]     = fmaxf(lo, 0.f);
        hs[(2 * op + 1) * QB + tid] = fmaxf(hi, 0.f);
    }
    __syncwarp();

    int lane = tid & 31, w = tid >> 5;

    // layer 2: 4 passes of 32 outputs; h read from shared (static addressing)
#pragma unroll 1
    for (int pass = 0; pass < 4; pass++) {
        ull acc[16];
#pragma unroll
        for (int j = 0; j < 16; j++)
            acc[j] = *(const ull*)&sm[OFF_B2 + pass * 32 + 2 * j];

#pragma unroll 8
        for (int k = 0; k < HID; k++) {
            float hk = hs[k * QB + tid];
            ull hk2 = pk2(hk, hk);
            const float* wr = &sm[OFF_W2 + k * OUT + pass * 32];
#pragma unroll
            for (int jj = 0; jj < 8; jj++) {
                ulonglong2 wv = *(const ulonglong2*)(wr + 4 * jj);
                acc[2 * jj]     = fma2(hk2, wv.x, acc[2 * jj]);
                acc[2 * jj + 1] = fma2(hk2, wv.y, acc[2 * jj + 1]);
            }
        }

#pragma unroll
        for (int j = 0; j < 16; j++) {
            float lo, hi; upk2(lo, hi, acc[j]);
            sm[OFF_STG + (2 * j) * STG_STRIDE + tid]     = fmaxf(lo, 0.f);
            sm[OFF_STG + (2 * j + 1) * STG_STRIDE + tid] = fmaxf(hi, 0.f);
        }
        __syncthreads();

        // coalesced store: warp w handles query it*4 + w, lane = output index
#pragma unroll 4
        for (int it = 0; it < 32; it++) {
            int ql = it * 4 + w;
            int gq = qb + ql;
            if (gq < Qn)
                out[(size_t)gq * OUT + pass * 32 + lane] =
                    sm[OFF_STG + lane * STG_STRIDE + ql];
        }
        __syncthreads();
    }
}

// ---------------- launch ----------------
extern "C" void kernel_launch(void* const* d_in, const int* in_sizes, int n_in,
                              void* d_out, int out_size) {
    const float* geom = (const float*)d_in[0];
    const float* lq   = (const float*)d_in[1];
    const int*   nidx = (const int*)d_in[2];
    const int*   rs   = (const int*)d_in[3];
    const float* W1   = (const float*)d_in[4];
    const float* b1   = (const float*)d_in[5];
    const float* W2   = (const float*)d_in[6];
    const float* b2   = (const float*)d_in[7];
    float* out = (float*)d_out;

    int nnodes = in_sizes[0] / 3;
    int Qn = in_sizes[3] - 1;

    prep_kernel<<<(nnodes + 255) / 256, 256>>>(geom, nnodes);
    moments_feat_kernel<<<(Qn + 255) / 256, 256>>>(lq, nidx, rs, Qn);

    cudaFuncSetAttribute(mlp_kernel, cudaFuncAttributeMaxDynamicSharedMemorySize,
                         MLP_SMEM_BYTES);
    mlp_kernel<<<(Qn + QB - 1) / QB, QB, MLP_SMEM_BYTES>>>(W1, b1, W2, b2, out, Qn);
}

// round 5
// speedup vs baseline: 1.1614x; 1.1614x over previous
#include <cuda_runtime.h>
#include <cuda_bf16.h>
#include <math.h>

#define N_NODES_MAX 200000
#define N_QUERY_MAX 131072
#define FEAT 9
#define HID 64
#define OUT 128

typedef unsigned long long ull;

// ---------------- static device scratch ----------------
__device__ float4 g_geom4[N_NODES_MAX];
__device__ float  g_feat[FEAT * N_QUERY_MAX];   // column-major [FEAT][Q]
__device__ double g_sums[2 * FEAT];

// ---------------- f32x2 helpers ----------------
__device__ __forceinline__ ull pk2(float lo, float hi) {
    ull r; asm("mov.b64 %0,{%1,%2};" : "=l"(r) : "f"(lo), "f"(hi)); return r;
}
__device__ __forceinline__ void upk2(float& lo, float& hi, ull v) {
    asm("mov.b64 {%0,%1},%2;" : "=f"(lo), "=f"(hi) : "l"(v));
}
__device__ __forceinline__ ull fma2(ull a, ull b, ull c) {
    ull d; asm("fma.rn.f32x2 %0,%1,%2,%3;" : "=l"(d) : "l"(a), "l"(b), "l"(c));
    return d;
}

// ---------------- K1: pad geometry + zero accumulators ----------------
__global__ void prep_kernel(const float* __restrict__ geom, int n) {
    int i = blockIdx.x * blockDim.x + threadIdx.x;
    if (blockIdx.x == 0 && threadIdx.x < 2 * FEAT) g_sums[threadIdx.x] = 0.0;
    if (i < n) {
        float4 p;
        p.x = geom[3 * i + 0];
        p.y = geom[3 * i + 1];
        p.z = geom[3 * i + 2];
        p.w = 0.f;
        g_geom4[i] = p;
    }
}

// ---------------- dummy (profiler alignment) ----------------
__global__ void dummy_kernel() {}

// ---------------- K2: fused moments + features + column reduction ----------------
__global__ __launch_bounds__(256)
void moments_feat_kernel(const float* __restrict__ lq,
                         const int* __restrict__ nidx,
                         const int* __restrict__ rs,
                         int Qn) {
    int q = blockIdx.x * blockDim.x + threadIdx.x;
    bool valid = (q < Qn);
    int qc = valid ? q : (Qn - 1);

    float f[FEAT];
#pragma unroll
    for (int i = 0; i < FEAT; i++) f[i] = 0.f;

    {
        int start = rs[qc];
        int end   = rs[qc + 1];
        int cnt   = end - start;

        float qx = __ldg(&lq[3 * qc + 0]);
        float qy = __ldg(&lq[3 * qc + 1]);
        float qz = __ldg(&lq[3 * qc + 2]);

        float sd = 0.f, sd2 = 0.f;
        float sx = 0.f, sy = 0.f, sz = 0.f;
        float sxx = 0.f, sxy = 0.f, sxz = 0.f, syy = 0.f, syz = 0.f, szz = 0.f;

        if (cnt == 32 && (start & 3) == 0) {
            const int4* ip = (const int4*)(nidx + start);
            int4 iv[8];
#pragma unroll
            for (int i = 0; i < 8; i++) iv[i] = __ldg(&ip[i]);
            const int* idf = (const int*)iv;
#pragma unroll
            for (int e = 0; e < 32; e++) {
                float4 p = g_geom4[idf[e]];
                float dx = p.x - qx, dy = p.y - qy, dz = p.z - qz;
                float d2 = dx * dx + dy * dy + dz * dz;
                sd  += sqrtf(d2);
                sd2 += d2;
                sx += p.x; sy += p.y; sz += p.z;
                sxx += p.x * p.x; sxy += p.x * p.y; sxz += p.x * p.z;
                syy += p.y * p.y; syz += p.y * p.z; szz += p.z * p.z;
            }
        } else {
            for (int e = start; e < end; e++) {
                int id = __ldg(&nidx[e]);
                float4 p = g_geom4[id];
                float dx = p.x - qx, dy = p.y - qy, dz = p.z - qz;
                float d2 = dx * dx + dy * dy + dz * dz;
                sd  += sqrtf(d2);
                sd2 += d2;
                sx += p.x; sy += p.y; sz += p.z;
                sxx += p.x * p.x; sxy += p.x * p.y; sxz += p.x * p.z;
                syy += p.y * p.y; syz += p.y * p.z; szz += p.z * p.z;
            }
        }

        if (valid && cnt > 0) {
            float fcnt = (float)cnt;
            float inv = 1.f / fmaxf(fcnt, 1.f);

            float davg = sd * inv;
            float ex2  = sd2 * inv;
            float dvar = fmaxf(ex2 - davg * davg, 0.f);

            float cx = sx * inv, cy = sy * inv, cz = sz * inv;

            float a = sxx * inv - cx * cx;
            float b = syy * inv - cy * cy;
            float c = szz * inv - cz * cz;
            float d = sxy * inv - cx * cy;
            float e = sxz * inv - cx * cz;
            float ff = syz * inv - cy * cz;

            float e1, e2, e3;
            float p1 = d * d + e * e + ff * ff;
            float qm = (a + b + c) * (1.f / 3.f);
            float aa = a - qm, bb = b - qm, cc = c - qm;
            float p2 = aa * aa + bb * bb + cc * cc + 2.f * p1;
            if (p2 <= 1e-22f) {
                e1 = e2 = e3 = qm;
            } else {
                float p = sqrtf(p2 * (1.f / 6.f));
                float ipv = 1.f / p;
                float b11 = aa * ipv, b22 = bb * ipv, b33 = cc * ipv;
                float b12 = d * ipv, b13 = e * ipv, b23 = ff * ipv;
                float r = 0.5f * (b11 * (b22 * b33 - b23 * b23)
                                - b12 * (b12 * b33 - b23 * b13)
                                + b13 * (b12 * b23 - b22 * b13));
                r = fminf(fmaxf(r, -1.f), 1.f);
                float phi = acosf(r) * (1.f / 3.f);
                e1 = qm + 2.f * p * cosf(phi);
                e3 = qm + 2.f * p * cosf(phi + 2.0943951023931953f);
                e2 = 3.f * qm - e1 - e3;
            }

            f[0] = fcnt; f[1] = davg; f[2] = dvar;
            f[3] = cx - qx; f[4] = cy - qy; f[5] = cz - qz;
            f[6] = e1; f[7] = e2; f[8] = e3;
        }
    }

    if (valid) {
#pragma unroll
        for (int i = 0; i < FEAT; i++) g_feat[i * N_QUERY_MAX + q] = f[i];
    }

    // block reduction of column sums/sumsqs in double
    double s[FEAT], s2[FEAT];
#pragma unroll
    for (int i = 0; i < FEAT; i++) {
        double v = valid ? (double)f[i] : 0.0;
        s[i] = v; s2[i] = v * v;
    }
#pragma unroll
    for (int i = 0; i < FEAT; i++) {
#pragma unroll
        for (int o = 16; o; o >>= 1) {
            s[i]  += __shfl_xor_sync(0xffffffffu, s[i], o);
            s2[i] += __shfl_xor_sync(0xffffffffu, s2[i], o);
        }
    }

    __shared__ double red[8][2 * FEAT];
    int warp = threadIdx.x >> 5, lane = threadIdx.x & 31;
    if (lane == 0) {
#pragma unroll
        for (int i = 0; i < FEAT; i++) {
            red[warp][i] = s[i];
            red[warp][FEAT + i] = s2[i];
        }
    }
    __syncthreads();
    if (threadIdx.x < 2 * FEAT) {
        double t = 0.0;
#pragma unroll
        for (int w = 0; w < 8; w++) t += red[w][threadIdx.x];
        atomicAdd(&g_sums[threadIdx.x], t);
    }
}

// ---------------- K3: fused MLP (R2 structure: full unroll, h in regs) ----------------
#define OFF_W2   0                     // 8192
#define OFF_W1   (OFF_W2 + HID * OUT)  // 576
#define OFF_B1   (OFF_W1 + FEAT * HID) // 64
#define OFF_B2   (OFF_B1 + HID)        // 128
#define OFF_NRM  (OFF_B2 + OUT)        // 32 (mean[9], invstd[9], pad)
#define OFF_STG  (OFF_NRM + 32)        // 32 * 129
#define STG_STRIDE 129
#define MLP_SMEM_FLOATS (OFF_STG + 32 * STG_STRIDE)
#define MLP_SMEM_BYTES  (MLP_SMEM_FLOATS * 4)
#define QB 128

__global__ __launch_bounds__(QB, 3)
void mlp_kernel(const float* __restrict__ gW1, const float* __restrict__ gb1,
                const float* __restrict__ gW2, const float* __restrict__ gb2,
                float* __restrict__ out, int Qn) {
    extern __shared__ float sm[];
    int tid = threadIdx.x;

    {
        const float4* w2v = (const float4*)gW2;
        float4* d = (float4*)&sm[OFF_W2];
#pragma unroll
        for (int i = 0; i < (HID * OUT / 4) / QB; i++)
            d[tid + i * QB] = w2v[tid + i * QB];
        for (int i = tid; i < FEAT * HID; i += QB) sm[OFF_W1 + i] = gW1[i];
        if (tid < HID) sm[OFF_B1 + tid] = gb1[tid];
        if (tid < OUT) sm[OFF_B2 + tid] = gb2[tid];
        if (tid < FEAT) {
            double Qd = (double)Qn;
            double mean = g_sums[tid] / Qd;
            double var = (g_sums[FEAT + tid] - Qd * mean * mean) / (Qd - 1.0);
            if (var < 0.0) var = 0.0;
            double sd = sqrt(var);
            sm[OFF_NRM + tid] = (float)mean;
            sm[OFF_NRM + FEAT + tid] = (sd < 1e-6) ? 1.0f : (float)(1.0 / sd);
        }
    }
    __syncthreads();

    int qb = blockIdx.x * QB;
    int q = qb + tid;
    int qc = (q < Qn) ? q : (Qn - 1);

    // normalized features (coalesced column-major loads), splat-packed
    ull fnp[FEAT];
#pragma unroll
    for (int i = 0; i < FEAT; i++) {
        float v = (g_feat[i * N_QUERY_MAX + qc] - sm[OFF_NRM + i]) * sm[OFF_NRM + FEAT + i];
        fnp[i] = pk2(v, v);
    }

    // layer 1: h[64] in registers (static indexing only)
    float h[HID];
#pragma unroll
    for (int op = 0; op < HID / 2; op++) {
        ull acc = *(const ull*)&sm[OFF_B1 + 2 * op];
#pragma unroll
        for (int ff = 0; ff < FEAT; ff++)
            acc = fma2(fnp[ff], *(const ull*)&sm[OFF_W1 + ff * HID + 2 * op], acc);
        float lo, hi; upk2(lo, hi, acc);
        h[2 * op]     = fmaxf(lo, 0.f);
        h[2 * op + 1] = fmaxf(hi, 0.f);
    }

    int lane = tid & 31, w = tid >> 5;

    // layer 2: 4 passes of 32 outputs, k-loop FULLY unrolled (R2 structure)
#pragma unroll 1
    for (int pass = 0; pass < 4; pass++) {
        ull acc[16];
#pragma unroll
        for (int j = 0; j < 16; j++)
            acc[j] = *(const ull*)&sm[OFF_B2 + pass * 32 + 2 * j];

#pragma unroll
        for (int k = 0; k < HID; k++) {
            ull hk = pk2(h[k], h[k]);
            const float* wr = &sm[OFF_W2 + k * OUT + pass * 32];
#pragma unroll
            for (int jj = 0; jj < 8; jj++) {
                ulonglong2 wv = *(const ulonglong2*)(wr + 4 * jj);
                acc[2 * jj]     = fma2(hk, wv.x, acc[2 * jj]);
                acc[2 * jj + 1] = fma2(hk, wv.y, acc[2 * jj + 1]);
            }
        }

#pragma unroll
        for (int j = 0; j < 16; j++) {
            float lo, hi; upk2(lo, hi, acc[j]);
            sm[OFF_STG + (2 * j) * STG_STRIDE + tid]     = fmaxf(lo, 0.f);
            sm[OFF_STG + (2 * j + 1) * STG_STRIDE + tid] = fmaxf(hi, 0.f);
        }
        __syncthreads();

#pragma unroll 4
        for (int it = 0; it < 32; it++) {
            int ql = it * 4 + w;
            int gq = qb + ql;
            if (gq < Qn)
                out[(size_t)gq * OUT + pass * 32 + lane] =
                    sm[OFF_STG + lane * STG_STRIDE + ql];
        }
        __syncthreads();
    }
}

// ---------------- launch ----------------
// Order chosen so mlp_kernel sits at global launch index 3 (the slot ncu's
// -s 5 -c 1 has captured in every round so far): prep(0), dummy(1),
// moments(2), mlp(3).
extern "C" void kernel_launch(void* const* d_in, const int* in_sizes, int n_in,
                              void* d_out, int out_size) {
    const float* geom = (const float*)d_in[0];
    const float* lq   = (const float*)d_in[1];
    const int*   nidx = (const int*)d_in[2];
    const int*   rs   = (const int*)d_in[3];
    const float* W1   = (const float*)d_in[4];
    const float* b1   = (const float*)d_in[5];
    const float* W2   = (const float*)d_in[6];
    const float* b2   = (const float*)d_in[7];
    float* out = (float*)d_out;

    int nnodes = in_sizes[0] / 3;
    int Qn = in_sizes[3] - 1;

    prep_kernel<<<(nnodes + 255) / 256, 256>>>(geom, nnodes);
    dummy_kernel<<<1, 32>>>();
    moments_feat_kernel<<<(Qn + 255) / 256, 256>>>(lq, nidx, rs, Qn);

    cudaFuncSetAttribute(mlp_kernel, cudaFuncAttributeMaxDynamicSharedMemorySize,
                         MLP_SMEM_BYTES);
    mlp_kernel<<<(Qn + QB - 1) / QB, QB, MLP_SMEM_BYTES>>>(W1, b1, W2, b2, out, Qn);
}